// round 11
// baseline (speedup 1.0000x reference)
#include <cuda_runtime.h>
#include <cuda_bf16.h>
#include <cuda_fp16.h>
#include <cstdint>

// ---------------------------------------------------------------------------
// Problem constants
// ---------------------------------------------------------------------------
#define B_    32
#define C_    128
#define CIN_  64
#define COUT_ 128
#define H_    128
#define W_    128
#define HW_   (H_ * W_)
#define NCHUNK 9             // one K=64 chunk per 3x3 tap, fp16 single-pass

// ---------------------------------------------------------------------------
// Device scratch (static allocations only)
// ---------------------------------------------------------------------------
__device__ float    g_chsum[B_ * C_];
__device__ int      g_idx[B_ * CIN_];
// Xf16[b][y][x][ci] fp16, 64 ci = 128B per pixel (67 MB)
__device__ __align__(128) __half g_Xf16[(size_t)B_ * H_ * W_ * CIN_];
// Wf16: 9 chunks x [128 couts x 64 k] fp16 linear (147 KB)
__device__ __align__(128) __half g_Wf16[NCHUNK * COUT_ * 64];

// ---------------------------------------------------------------------------
// Helpers
// ---------------------------------------------------------------------------
__device__ __forceinline__ uint32_t smem_u32(const void* p) {
    uint32_t a;
    asm("{ .reg .u64 t; cvta.to.shared.u64 t, %1; cvt.u32.u64 %0, t; }" : "=r"(a) : "l"(p));
    return a;
}

__device__ __forceinline__ void ldsm_x4(uint32_t& r0, uint32_t& r1,
                                        uint32_t& r2, uint32_t& r3, uint32_t addr) {
    asm volatile("ldmatrix.sync.aligned.m8n8.x4.shared.b16 {%0,%1,%2,%3}, [%4];"
                 : "=r"(r0), "=r"(r1), "=r"(r2), "=r"(r3) : "r"(addr));
}

__device__ __forceinline__ void mma16816(float* d, uint32_t a0, uint32_t a1,
                                         uint32_t a2, uint32_t a3,
                                         uint32_t b0, uint32_t b1) {
    asm volatile(
        "mma.sync.aligned.m16n8k16.row.col.f32.f16.f16.f32 "
        "{%0,%1,%2,%3}, {%4,%5,%6,%7}, {%8,%9}, {%0,%1,%2,%3};"
        : "+f"(d[0]), "+f"(d[1]), "+f"(d[2]), "+f"(d[3])
        : "r"(a0), "r"(a1), "r"(a2), "r"(a3), "r"(b0), "r"(b1));
}

// ---------------------------------------------------------------------------
// Kernel 1: per-channel sums
// ---------------------------------------------------------------------------
__global__ __launch_bounds__(256) void chsum_kernel(const float* __restrict__ x) {
    const int ch = blockIdx.x;
    const float4* p = reinterpret_cast<const float4*>(x) + (size_t)ch * (HW_ / 4);
    float s = 0.f;
    for (int i = threadIdx.x; i < HW_ / 4; i += 256) {
        float4 v = p[i];
        s += (v.x + v.y) + (v.z + v.w);
    }
    #pragma unroll
    for (int o = 16; o; o >>= 1) s += __shfl_down_sync(0xffffffffu, s, o);
    __shared__ float red[8];
    if ((threadIdx.x & 31) == 0) red[threadIdx.x >> 5] = s;
    __syncthreads();
    if (threadIdx.x < 8) {
        s = red[threadIdx.x];
        #pragma unroll
        for (int o = 4; o; o >>= 1) s += __shfl_down_sync(0xffu, s, o);
        if (threadIdx.x == 0) g_chsum[ch] = s;
    }
}

// ---------------------------------------------------------------------------
// Kernel 2: select (blocks 0..31) + weight fp16 reorder (blocks 32..)
// ---------------------------------------------------------------------------
__global__ __launch_bounds__(256) void select_wprep_kernel(const float* __restrict__ w) {
    if (blockIdx.x < B_) {
        if (threadIdx.x >= C_) return;
        const int b = blockIdx.x, c = threadIdx.x;
        __shared__ float s[C_];
        s[c] = g_chsum[b * C_ + c];
        __syncthreads();
        const float mine = s[c];
        int rank = 0;
        #pragma unroll 8
        for (int j = 0; j < C_; j++) {
            float v = s[j];
            rank += (v < mine) || (v == mine && j < c);
        }
        if (rank < CIN_) g_idx[b * CIN_ + rank] = c;
    } else {
        int t = (blockIdx.x - B_) * 256 + threadIdx.x;
        if (t >= NCHUNK * COUT_ * 64) return;
        int tap = t >> 13;               // /8192
        int r = (t >> 6) & 127;          // cout
        int k = t & 63;                  // ci
        g_Wf16[t] = __float2half_rn(w[r * (CIN_ * 9) + k * 9 + tap]);
    }
}

// ---------------------------------------------------------------------------
// Kernel 3: gather selected channels, CHW->HWC transpose, fp16 convert
// ---------------------------------------------------------------------------
__global__ __launch_bounds__(256) void gather_split_kernel(const float* __restrict__ x) {
    const int y = blockIdx.x, b = blockIdx.y;
    const int tid = threadIdx.x;
    __shared__ float sv[CIN_][W_ + 1];

    for (int i = tid; i < CIN_ * W_; i += 256) {
        int ci = i >> 7, xx = i & 127;
        int src_c = g_idx[b * CIN_ + ci];
        sv[ci][xx] = x[(((size_t)b * C_ + src_c) * H_ + y) * W_ + xx];
    }
    __syncthreads();

    uint32_t* dst = reinterpret_cast<uint32_t*>(
        g_Xf16 + ((size_t)(b * H_ + y)) * W_ * CIN_);
    for (int o = tid; o < W_ * (CIN_ / 2); o += 256) {
        int xx = o >> 5, cw = o & 31;
        __half h0 = __float2half_rn(sv[2 * cw][xx]);
        __half h1 = __float2half_rn(sv[2 * cw + 1][xx]);
        uint32_t w0 = (uint32_t)*reinterpret_cast<unsigned short*>(&h0) |
                      ((uint32_t)*reinterpret_cast<unsigned short*>(&h1) << 16);
        dst[o] = w0;
    }
}

// ---------------------------------------------------------------------------
// Kernel 4: conv implicit GEMM, mma.sync fp16, ldmatrix fragment loads.
//   CTA = (batch b, 2 output rows). M=256 pixels, N=128 couts. 16 warps
//   m32n64 (wm 0..7, wn 0..1). 1 CTA/SM.
//   ALL SMEM loaded once: 9 B chunks resident (147KB) + one 4-input-row A
//   window (520 rows x 128B = 66.5KB). No buffer hazards -> only 3
//   wait_group+barrier pairs total (B arrives in 3 groups of 3 chunks).
// ---------------------------------------------------------------------------
#define A_WIN_ROWS 520            // 4 input rows x 130 padded pixels
#define A_WIN_BYTES (A_WIN_ROWS * 128)
#define B_ALL_BYTES (NCHUNK * 16384)
#define SMEM_TOTAL (A_WIN_BYTES + B_ALL_BYTES)   // 66560 + 147456 = 214016

extern __shared__ char dynsmem[];

__global__ __launch_bounds__(512, 1) void conv_mma_kernel(
    const float* __restrict__ bias, float* __restrict__ out)
{
    const int ytile = blockIdx.x;             // 0..63 (2 output rows)
    const int b = blockIdx.y;                 // 0..31
    const int y0 = ytile * 2;
    const int tid = threadIdx.x;
    const int wid = tid >> 5;                 // 0..15
    const int lane = tid & 31;
    const int g = lane >> 2;                  // 0..7
    const int t4 = lane & 3;                  // 0..3
    const int wm = wid & 7;                   // m tile 0..7 (rows of 32)
    const int wn = wid >> 3;                  // n tile 0..1 (cols of 64)
    const int yl = wm >> 2;                   // local output row 0/1

    const uint32_t Awin = smem_u32(dynsmem);
    const uint32_t Ball = Awin + A_WIN_BYTES;

    __shared__ float sbias[COUT_];
    if (tid < COUT_) sbias[tid] = bias[tid];

    // ldmatrix lane geometry
    const int laneA = lane & 15;              // row-in-16 for A matrices
    const int unitA_half = lane >> 4;         // +0/+1 16B unit
    const int laneB = (lane & 7) + ((lane >> 4) << 3);  // row-in-16 for B
    const int unitB_half = (lane >> 3) & 1;

    float acc[2][8][4];
    #pragma unroll
    for (int mt = 0; mt < 2; mt++)
        #pragma unroll
        for (int nt = 0; nt < 8; nt++)
            #pragma unroll
            for (int r = 0; r < 4; r++) acc[mt][nt][r] = 0.f;

    // ---- A window load (once): row r -> input row y0+r/130-1, pixel r%130-1
    {
        #pragma unroll
        for (int it = 0; it < 9; it++) {
            int i = tid + it * 512;
            if (i < A_WIN_ROWS * 8) {
                int r = i >> 3, j = i & 7;
                int inrow = r / 130;
                int xp = r - inrow * 130;
                int yy = y0 + inrow - 1;
                int xx = xp - 1;
                bool valid = ((unsigned)yy < (unsigned)H_) &&
                             ((unsigned)xx < (unsigned)W_);
                int yc = valid ? yy : 0, xc = valid ? xx : 0;
                const char* src = reinterpret_cast<const char*>(
                    g_Xf16 + (((size_t)(b * H_ + yc) * W_ + xc) * CIN_)) + j * 16;
                uint32_t dst = Awin + (uint32_t)r * 128u +
                               (uint32_t)((j * 16) ^ ((r & 7) << 4));
                uint32_t sz = valid ? 16u : 0u;
                asm volatile("cp.async.cg.shared.global [%0], [%1], 16, %2;"
                             :: "r"(dst), "l"(src), "r"(sz));
            }
        }
    }
    // ---- B chunk loads (once each); commit in 3 groups of 3 chunks
    auto prefetchB = [&](int t) {
        const char* wsrc = reinterpret_cast<const char*>(g_Wf16) + (size_t)t * 16384;
        const uint32_t bbase = Ball + (uint32_t)t * 16384u;
        #pragma unroll
        for (int it = 0; it < 2; it++) {
            int i = tid + it * 512;
            int r = i >> 3, j = i & 7;
            uint32_t dst = bbase + (uint32_t)r * 128u +
                           (uint32_t)((j * 16) ^ ((r & 7) << 4));
            asm volatile("cp.async.cg.shared.global [%0], [%1], 16, 16;"
                         :: "r"(dst), "l"(wsrc + (size_t)r * 128 + j * 16));
        }
    };
    prefetchB(0); prefetchB(1); prefetchB(2);
    asm volatile("cp.async.commit_group;" ::: "memory");   // G0 = A + B0..2
    prefetchB(3); prefetchB(4); prefetchB(5);
    asm volatile("cp.async.commit_group;" ::: "memory");   // G1 = B3..5
    prefetchB(6); prefetchB(7); prefetchB(8);
    asm volatile("cp.async.commit_group;" ::: "memory");   // G2 = B6..8

    for (int t = 0; t < NCHUNK; t++) {
        const int ky = t / 3;
        const int kx = t - ky * 3;
        if (kx == 0) {                         // stage boundary: B group ready
            if (ky == 0)      asm volatile("cp.async.wait_group 2;" ::: "memory");
            else if (ky == 1) asm volatile("cp.async.wait_group 1;" ::: "memory");
            else              asm volatile("cp.async.wait_group 0;" ::: "memory");
            __syncthreads();
        }

        const uint32_t Bb = Ball + (uint32_t)t * 16384u;
        // A window row: (yl+ky)*130 + x + kx, x = (wm&3)*32 + mt*16 + laneA
        const int rowA0 = (yl + ky) * 130 + (wm & 3) * 32 + laneA + kx;
        const int rowB0 = wn * 64 + laneB;

        uint32_t bf[2][8][2];
        auto loadB = [&](int ks, int which) {
            #pragma unroll
            for (int nt2 = 0; nt2 < 4; nt2++) {
                int row = rowB0 + nt2 * 16;
                uint32_t addr = Bb + (uint32_t)(row << 7) +
                    (uint32_t)((((ks * 2 + unitB_half) << 4)) ^ ((row & 7) << 4));
                ldsm_x4(bf[which][2 * nt2][0], bf[which][2 * nt2][1],
                        bf[which][2 * nt2 + 1][0], bf[which][2 * nt2 + 1][1], addr);
            }
        };

        loadB(0, 0);
        #pragma unroll
        for (int ks = 0; ks < 4; ks++) {
            const int cur = ks & 1;
            if (ks < 3) loadB(ks + 1, cur ^ 1);   // overlap with HMMAs below
            #pragma unroll
            for (int mt = 0; mt < 2; mt++) {
                int row = rowA0 + mt * 16;
                uint32_t addr = Awin + (uint32_t)(row << 7) +
                    (uint32_t)((((ks * 2 + unitA_half) << 4)) ^ ((row & 7) << 4));
                uint32_t a0, a1, a2, a3;
                ldsm_x4(a0, a1, a2, a3, addr);
                #pragma unroll
                for (int nt = 0; nt < 8; nt++)
                    mma16816(acc[mt][nt], a0, a1, a2, a3,
                             bf[cur][nt][0], bf[cur][nt][1]);
            }
        }
    }

    // ---- epilogue: direct STG.32 stores (each 8-lane g-group = 32B sector) ----
    const int yout = y0 + yl;
    #pragma unroll
    for (int mt = 0; mt < 2; mt++) {
        const int p0 = (wm & 3) * 32 + mt * 16 + g;       // pixel x
        #pragma unroll
        for (int nt = 0; nt < 8; nt++) {
            const int n0 = wn * 64 + nt * 8 + 2 * t4;
            const float bv0 = sbias[n0];
            const float bv1 = sbias[n0 + 1];
            float* o0 = out + (((size_t)b * COUT_ + n0) * H_ + yout) * W_;
            float* o1 = o0 + (size_t)HW_;     // n0+1
            o0[p0]     = acc[mt][nt][0] + bv0;
            o1[p0]     = acc[mt][nt][1] + bv1;
            o0[p0 + 8] = acc[mt][nt][2] + bv0;
            o1[p0 + 8] = acc[mt][nt][3] + bv1;
        }
    }
}

// ---------------------------------------------------------------------------
extern "C" void kernel_launch(void* const* d_in, const int* in_sizes, int n_in,
                              void* d_out, int out_size) {
    const float* x  = (const float*)d_in[0];   // [32,128,128,128]
    const float* w  = (const float*)d_in[1];   // [128,64,3,3]
    const float* bv = (const float*)d_in[2];   // [128]
    float* out = (float*)d_out;

    static bool attr_set = false;
    if (!attr_set) {
        cudaFuncSetAttribute(conv_mma_kernel,
                             cudaFuncAttributeMaxDynamicSharedMemorySize, SMEM_TOTAL);
        attr_set = true;
    }

    chsum_kernel<<<B_ * C_, 256>>>(x);
    select_wprep_kernel<<<B_ + (NCHUNK * COUT_ * 64 + 255) / 256, 256>>>(w);
    gather_split_kernel<<<dim3(H_, B_), 256>>>(x);
    conv_mma_kernel<<<dim3(H_ / 2, B_), 512, SMEM_TOTAL>>>(bv, out);
}

// round 12
// speedup vs baseline: 1.0454x; 1.0454x over previous
#include <cuda_runtime.h>
#include <cuda_bf16.h>
#include <cuda_fp16.h>
#include <cstdint>

// ---------------------------------------------------------------------------
// Problem constants
// ---------------------------------------------------------------------------
#define B_    32
#define C_    128
#define CIN_  64
#define COUT_ 128
#define H_    128
#define W_    128
#define HW_   (H_ * W_)
#define NCHUNK 9             // one K=64 chunk per 3x3 tap, fp16 single-pass

// ---------------------------------------------------------------------------
// Device scratch (static allocations only)
// ---------------------------------------------------------------------------
__device__ float    g_chsum[B_ * C_];
__device__ int      g_idx[B_ * CIN_];
// Xf16[b][y][x][ci] fp16, 64 ci = 128B per pixel (67 MB)
__device__ __align__(128) __half g_Xf16[(size_t)B_ * H_ * W_ * CIN_];
// Wf16: 9 chunks x [128 couts x 64 k] fp16 linear (147 KB)
__device__ __align__(128) __half g_Wf16[NCHUNK * COUT_ * 64];

// ---------------------------------------------------------------------------
// Helpers
// ---------------------------------------------------------------------------
__device__ __forceinline__ uint32_t smem_u32(const void* p) {
    uint32_t a;
    asm("{ .reg .u64 t; cvta.to.shared.u64 t, %1; cvt.u32.u64 %0, t; }" : "=r"(a) : "l"(p));
    return a;
}

__device__ __forceinline__ void ldsm_x4(uint32_t& r0, uint32_t& r1,
                                        uint32_t& r2, uint32_t& r3, uint32_t addr) {
    asm volatile("ldmatrix.sync.aligned.m8n8.x4.shared.b16 {%0,%1,%2,%3}, [%4];"
                 : "=r"(r0), "=r"(r1), "=r"(r2), "=r"(r3) : "r"(addr));
}

__device__ __forceinline__ void mma16816(float* d, uint32_t a0, uint32_t a1,
                                         uint32_t a2, uint32_t a3,
                                         uint32_t b0, uint32_t b1) {
    asm volatile(
        "mma.sync.aligned.m16n8k16.row.col.f32.f16.f16.f32 "
        "{%0,%1,%2,%3}, {%4,%5,%6,%7}, {%8,%9}, {%0,%1,%2,%3};"
        : "+f"(d[0]), "+f"(d[1]), "+f"(d[2]), "+f"(d[3])
        : "r"(a0), "r"(a1), "r"(a2), "r"(a3), "r"(b0), "r"(b1));
}

// ---------------------------------------------------------------------------
// Kernel 1: per-channel sums
// ---------------------------------------------------------------------------
__global__ __launch_bounds__(256) void chsum_kernel(const float* __restrict__ x) {
    const int ch = blockIdx.x;
    const float4* p = reinterpret_cast<const float4*>(x) + (size_t)ch * (HW_ / 4);
    float s = 0.f;
    for (int i = threadIdx.x; i < HW_ / 4; i += 256) {
        float4 v = p[i];
        s += (v.x + v.y) + (v.z + v.w);
    }
    #pragma unroll
    for (int o = 16; o; o >>= 1) s += __shfl_down_sync(0xffffffffu, s, o);
    __shared__ float red[8];
    if ((threadIdx.x & 31) == 0) red[threadIdx.x >> 5] = s;
    __syncthreads();
    if (threadIdx.x < 8) {
        s = red[threadIdx.x];
        #pragma unroll
        for (int o = 4; o; o >>= 1) s += __shfl_down_sync(0xffu, s, o);
        if (threadIdx.x == 0) g_chsum[ch] = s;
    }
}

// ---------------------------------------------------------------------------
// Kernel 2: select (blocks 0..31) + weight fp16 reorder (blocks 32..)
// ---------------------------------------------------------------------------
__global__ __launch_bounds__(256) void select_wprep_kernel(const float* __restrict__ w) {
    if (blockIdx.x < B_) {
        if (threadIdx.x >= C_) return;
        const int b = blockIdx.x, c = threadIdx.x;
        __shared__ float s[C_];
        s[c] = g_chsum[b * C_ + c];
        __syncthreads();
        const float mine = s[c];
        int rank = 0;
        #pragma unroll 8
        for (int j = 0; j < C_; j++) {
            float v = s[j];
            rank += (v < mine) || (v == mine && j < c);
        }
        if (rank < CIN_) g_idx[b * CIN_ + rank] = c;
    } else {
        int t = (blockIdx.x - B_) * 256 + threadIdx.x;
        if (t >= NCHUNK * COUT_ * 64) return;
        int tap = t >> 13;               // /8192
        int r = (t >> 6) & 127;          // cout
        int k = t & 63;                  // ci
        g_Wf16[t] = __float2half_rn(w[r * (CIN_ * 9) + k * 9 + tap]);
    }
}

// ---------------------------------------------------------------------------
// Kernel 3: gather selected channels, CHW->HWC transpose, fp16 convert
// ---------------------------------------------------------------------------
__global__ __launch_bounds__(256) void gather_split_kernel(const float* __restrict__ x) {
    const int y = blockIdx.x, b = blockIdx.y;
    const int tid = threadIdx.x;
    __shared__ float sv[CIN_][W_ + 1];

    for (int i = tid; i < CIN_ * W_; i += 256) {
        int ci = i >> 7, xx = i & 127;
        int src_c = g_idx[b * CIN_ + ci];
        sv[ci][xx] = x[(((size_t)b * C_ + src_c) * H_ + y) * W_ + xx];
    }
    __syncthreads();

    uint32_t* dst = reinterpret_cast<uint32_t*>(
        g_Xf16 + ((size_t)(b * H_ + y)) * W_ * CIN_);
    for (int o = tid; o < W_ * (CIN_ / 2); o += 256) {
        int xx = o >> 5, cw = o & 31;
        __half h0 = __float2half_rn(sv[2 * cw][xx]);
        __half h1 = __float2half_rn(sv[2 * cw + 1][xx]);
        uint32_t w0 = (uint32_t)*reinterpret_cast<unsigned short*>(&h0) |
                      ((uint32_t)*reinterpret_cast<unsigned short*>(&h1) << 16);
        dst[o] = w0;
    }
}

// ---------------------------------------------------------------------------
// Kernel 4: conv implicit GEMM, mma.sync fp16, warp tile m64 x n64.
//   CTA = (batch b, 2 output rows). M=256, N=128. 8 warps (wm 0..3, wn 0..1),
//   256 threads, 1 CTA/SM, 255 regs. B fragments reused across 4 m-subtiles
//   -> crossbar bytes/MAC halved vs m32n64.
//   ALL SMEM loaded once: 9 B chunks resident (147KB) + 4-input-row A window
//   (520 x 128B = 66.5KB). 3 wait+barrier pairs total.
// ---------------------------------------------------------------------------
#define A_WIN_ROWS 520            // 4 input rows x 130 padded pixels
#define A_WIN_BYTES (A_WIN_ROWS * 128)
#define B_ALL_BYTES (NCHUNK * 16384)
#define SMEM_TOTAL (A_WIN_BYTES + B_ALL_BYTES)   // 214016

extern __shared__ char dynsmem[];

__global__ __launch_bounds__(256, 1) void conv_mma_kernel(
    const float* __restrict__ bias, float* __restrict__ out)
{
    const int ytile = blockIdx.x;             // 0..63 (2 output rows)
    const int b = blockIdx.y;                 // 0..31
    const int y0 = ytile * 2;
    const int tid = threadIdx.x;
    const int wid = tid >> 5;                 // 0..7
    const int lane = tid & 31;
    const int g = lane >> 2;                  // 0..7
    const int t4 = lane & 3;                  // 0..3
    const int wm = wid & 3;                   // m64 tile 0..3 over M=256
    const int wn = wid >> 2;                  // n64 tile 0..1
    const int yl = wm >> 1;                   // local output row 0/1
    const int xbase = (wm & 1) * 64;          // pixel-x base of this m64 tile

    const uint32_t Awin = smem_u32(dynsmem);
    const uint32_t Ball = Awin + A_WIN_BYTES;

    __shared__ float sbias[COUT_];
    if (tid < COUT_) sbias[tid] = bias[tid];

    // ldmatrix lane geometry
    const int laneA = lane & 15;              // row-in-16 for A matrices
    const int unitA_half = lane >> 4;         // +0/+1 16B unit
    const int laneB = (lane & 7) + ((lane >> 4) << 3);  // row-in-16 for B
    const int unitB_half = (lane >> 3) & 1;

    float acc[4][8][4];
    #pragma unroll
    for (int mt = 0; mt < 4; mt++)
        #pragma unroll
        for (int nt = 0; nt < 8; nt++)
            #pragma unroll
            for (int r = 0; r < 4; r++) acc[mt][nt][r] = 0.f;

    // ---- A window load (once): row r -> input row y0+r/130-1, pixel r%130-1
    {
        #pragma unroll
        for (int it = 0; it < 17; it++) {
            int i = tid + it * 256;
            if (i < A_WIN_ROWS * 8) {
                int r = i >> 3, j = i & 7;
                int inrow = r / 130;
                int xp = r - inrow * 130;
                int yy = y0 + inrow - 1;
                int xx = xp - 1;
                bool valid = ((unsigned)yy < (unsigned)H_) &&
                             ((unsigned)xx < (unsigned)W_);
                int yc = valid ? yy : 0, xc = valid ? xx : 0;
                const char* src = reinterpret_cast<const char*>(
                    g_Xf16 + (((size_t)(b * H_ + yc) * W_ + xc) * CIN_)) + j * 16;
                uint32_t dst = Awin + (uint32_t)r * 128u +
                               (uint32_t)((j * 16) ^ ((r & 7) << 4));
                uint32_t sz = valid ? 16u : 0u;
                asm volatile("cp.async.cg.shared.global [%0], [%1], 16, %2;"
                             :: "r"(dst), "l"(src), "r"(sz));
            }
        }
    }
    // ---- B chunk loads (once each); commit in 3 groups of 3 chunks
    auto prefetchB = [&](int t) {
        const char* wsrc = reinterpret_cast<const char*>(g_Wf16) + (size_t)t * 16384;
        const uint32_t bbase = Ball + (uint32_t)t * 16384u;
        #pragma unroll
        for (int it = 0; it < 4; it++) {
            int i = tid + it * 256;
            int r = i >> 3, j = i & 7;
            uint32_t dst = bbase + (uint32_t)r * 128u +
                           (uint32_t)((j * 16) ^ ((r & 7) << 4));
            asm volatile("cp.async.cg.shared.global [%0], [%1], 16, 16;"
                         :: "r"(dst), "l"(wsrc + (size_t)r * 128 + j * 16));
        }
    };
    prefetchB(0); prefetchB(1); prefetchB(2);
    asm volatile("cp.async.commit_group;" ::: "memory");   // G0 = A + B0..2
    prefetchB(3); prefetchB(4); prefetchB(5);
    asm volatile("cp.async.commit_group;" ::: "memory");   // G1 = B3..5
    prefetchB(6); prefetchB(7); prefetchB(8);
    asm volatile("cp.async.commit_group;" ::: "memory");   // G2 = B6..8

    for (int t = 0; t < NCHUNK; t++) {
        const int ky = t / 3;
        const int kx = t - ky * 3;
        if (kx == 0) {                         // stage boundary: B group ready
            if (ky == 0)      asm volatile("cp.async.wait_group 2;" ::: "memory");
            else if (ky == 1) asm volatile("cp.async.wait_group 1;" ::: "memory");
            else              asm volatile("cp.async.wait_group 0;" ::: "memory");
            __syncthreads();
        }

        const uint32_t Bb = Ball + (uint32_t)t * 16384u;
        // A window row: (yl+ky)*130 + xbase + mt*16 + laneA + kx
        const int rowA0 = (yl + ky) * 130 + xbase + laneA + kx;
        const int rowB0 = wn * 64 + laneB;

        uint32_t bf[2][8][2];
        auto loadB = [&](int ks, int which) {
            #pragma unroll
            for (int nt2 = 0; nt2 < 4; nt2++) {
                int row = rowB0 + nt2 * 16;
                uint32_t addr = Bb + (uint32_t)(row << 7) +
                    (uint32_t)((((ks * 2 + unitB_half) << 4)) ^ ((row & 7) << 4));
                ldsm_x4(bf[which][2 * nt2][0], bf[which][2 * nt2][1],
                        bf[which][2 * nt2 + 1][0], bf[which][2 * nt2 + 1][1], addr);
            }
        };

        loadB(0, 0);
        #pragma unroll
        for (int ks = 0; ks < 4; ks++) {
            const int cur = ks & 1;
            if (ks < 3) loadB(ks + 1, cur ^ 1);   // overlap with HMMAs below
            #pragma unroll
            for (int mt = 0; mt < 4; mt++) {
                int row = rowA0 + mt * 16;
                uint32_t addr = Awin + (uint32_t)(row << 7) +
                    (uint32_t)((((ks * 2 + unitA_half) << 4)) ^ ((row & 7) << 4));
                uint32_t a0, a1, a2, a3;
                ldsm_x4(a0, a1, a2, a3, addr);
                #pragma unroll
                for (int nt = 0; nt < 8; nt++)
                    mma16816(acc[mt][nt], a0, a1, a2, a3,
                             bf[cur][nt][0], bf[cur][nt][1]);
            }
        }
    }

    // ---- epilogue: direct STG.32 stores (each 8-lane g-group = 32B sector) ----
    const int yout = y0 + yl;
    #pragma unroll
    for (int mt = 0; mt < 4; mt++) {
        const int p0 = xbase + mt * 16 + g;               // pixel x
        #pragma unroll
        for (int nt = 0; nt < 8; nt++) {
            const int n0 = wn * 64 + nt * 8 + 2 * t4;
            const float bv0 = sbias[n0];
            const float bv1 = sbias[n0 + 1];
            float* o0 = out + (((size_t)b * COUT_ + n0) * H_ + yout) * W_;
            float* o1 = o0 + (size_t)HW_;     // n0+1
            o0[p0]     = acc[mt][nt][0] + bv0;
            o1[p0]     = acc[mt][nt][1] + bv1;
            o0[p0 + 8] = acc[mt][nt][2] + bv0;
            o1[p0 + 8] = acc[mt][nt][3] + bv1;
        }
    }
}

// ---------------------------------------------------------------------------
extern "C" void kernel_launch(void* const* d_in, const int* in_sizes, int n_in,
                              void* d_out, int out_size) {
    const float* x  = (const float*)d_in[0];   // [32,128,128,128]
    const float* w  = (const float*)d_in[1];   // [128,64,3,3]
    const float* bv = (const float*)d_in[2];   // [128]
    float* out = (float*)d_out;

    static bool attr_set = false;
    if (!attr_set) {
        cudaFuncSetAttribute(conv_mma_kernel,
                             cudaFuncAttributeMaxDynamicSharedMemorySize, SMEM_TOTAL);
        attr_set = true;
    }

    chsum_kernel<<<B_ * C_, 256>>>(x);
    select_wprep_kernel<<<B_ + (NCHUNK * COUT_ * 64 + 255) / 256, 256>>>(w);
    gather_split_kernel<<<dim3(H_, B_), 256>>>(x);
    conv_mma_kernel<<<dim3(H_ / 2, B_), 256, SMEM_TOTAL>>>(bv, out);
}